// round 13
// baseline (speedup 1.0000x reference)
#include <cuda_runtime.h>

#define NX     20      // x in [0, 20)
#define KSER   40      // fp32 series terms (setup); z<=0.75 tail ~1e-5
#define DEG    8       // polynomial degree of log(2F1) fit
#define NC     9       // DEG+1 coefficients / Chebyshev nodes
#define NINVS  59      // distinct 1/(a+b+j), j = x+k-1 in [0, 57]
// fit interval z in [0, 0.75]:  t = z*8/3 - 1
#define ZC     0.375f
#define ZH     0.375f
#define TSCALE 2.6666667f

#define THREADS 768
#define NBLOCKS 296    // 2 CTAs/SM x 148 SMs; single wave on 148- and 152-SM parts

// Chebyshev -> monomial conversion matrix, MC[j][k] = coeff of t^k in T_j (exact).
__constant__ float MC[NC][NC] = {
    { 1,  0,   0,    0,   0,    0,    0,    0,   0},
    { 0,  1,   0,    0,   0,    0,    0,    0,   0},
    {-1,  0,   2,    0,   0,    0,    0,    0,   0},
    { 0, -3,   0,    4,   0,    0,    0,    0,   0},
    { 1,  0,  -8,    0,   8,    0,    0,    0,   0},
    { 0,  5,   0,  -20,   0,   16,    0,    0,   0},
    {-1,  0,  18,    0, -48,    0,   32,    0,   0},
    { 0, -7,   0,   56,   0, -112,    0,   64,   0},
    { 1,  0, -32,    0, 160,    0, -256,    0, 128},
};

__device__ __forceinline__ float eval_elem(int x, float t_x, float T,
                                           float r, float alpha,
                                           float r_la, float c0,
                                           const float* sP) {
    float aT = T + alpha;
    float lT = __logf(aT);
    float dt = T - t_x;
    float z  = dt * __frcp_rn(aT);
    float lz = __logf(z);
    float t  = __fmaf_rn(z, TSCALE, -1.0f);
    const float* col = sP + x;                // x < NX guaranteed; stride NX over k
    float sacc = col[DEG * NX];
#pragma unroll
    for (int k = DEG - 1; k >= 0; k--)
        sacc = __fmaf_rn(sacc, t, col[k * NX]);
    float common = __fmaf_rn(-r, lT, r_la);
    float ll1 = __fmaf_rn(__int2float_rn(x), lz, common + sacc);
    float ll0 = common + c0;
    return (x == 0) ? ll0 : ll1;
}

__global__ __launch_bounds__(THREADS, 2) void bgnbd_kernel(
    const int4*   __restrict__ xin,
    const float4* __restrict__ txin,
    const float4* __restrict__ Tin,
    float4*       __restrict__ out,
    const float*  __restrict__ lr,
    const float*  __restrict__ lal,
    const float*  __restrict__ la,
    const float*  __restrict__ lb,
    int n)
{
    __shared__ float invS[NINVS];       // 1/(a+b+j)
    __shared__ float inv64[KSER];       // 1/(k+1)
    __shared__ float cosM[NC * NC];     // w_j * cos(pi j (i+0.5)/NC), [j][i]
    __shared__ float Amat[NC * NC];     // A[k][i] = sum_j MC[j][k] * cosM[j][i]
    __shared__ float Ctab[KSER * NX];   // series coeffs C_k(x), [k][x]
    __shared__ float fnode[NC * NX];    // log 2F1 at node i for x, [i][x]
    __shared__ float gsh[NX];           // lgamma combo per x
    __shared__ float sP[NC * NX];       // monomial coeffs (+gsh in k=0), [k][x]

    const float PI = 3.14159265358979323846f;
    int tid = threadIdx.x;

    int stride  = gridDim.x * blockDim.x;
    int ngroups = n >> 2;
    int g = blockIdx.x * blockDim.x + tid;

    // ---- Early prefetch of first group (3 LDG.128), overlaps setup ----
    int4 xa; float4 ta, Ta;
    if (g < ngroups) {
        xa = xin[g];
        ta = txin[g];
        Ta = Tin[g];
    }

    // Scalars (broadcast loads)
    float log_alpha = lal[0];
    float r     = __expf(lr[0]);
    float a     = __expf(la[0]);
    float b     = __expf(lb[0]);
    float alpha = __expf(log_alpha);
    float ab    = a + b;
    float r_la  = r * log_alpha;
    float c0    = logf(b) - logf(ab);

    // ---- Stage 1 (disjoint thread ranges, fully parallel) ----
    if (tid < NINVS) {
        invS[tid] = __frcp_rn(ab + (float)tid);
    } else if (tid >= 64 && tid < 64 + KSER) {
        int k = tid - 64;
        inv64[k] = __frcp_rn((float)(k + 1));
    } else if (tid >= 128 && tid < 128 + NC * NC) {
        int id = tid - 128;
        int j = id / NC, i = id % NC;
        float w = (j == 0) ? (1.0f / NC) : (2.0f / NC);
        cosM[id] = w * cosf(PI * (float)j * ((float)i + 0.5f) / (float)NC);
    } else if (tid >= 256 && tid < 256 + NX) {
        int x = tid - 256;
        float xf = (float)x;
        gsh[x] = lgammaf(r + xf) - lgammaf(r) - lgammaf(xf + 1.0f)
               + logf(a) + lgammaf(ab) - lgammaf(a)
               - lgammaf(ab + xf) + lgammaf(a + xf);
    }
    __syncthreads();

    // ---- Stage 2: serial C-table (threads 0-19)  ||  A = MC^T * cosM (threads 128+) ----
    if (tid < NX) {
        int x = tid;
        float xf = (float)x;
        float p = r + xf, q = a;
        float c = 1.0f;
        Ctab[0 * NX + x] = 1.0f;
        for (int k = 1; k < KSER; k++) {
            float km1 = (float)(k - 1);
            c *= (p + km1) * (q + km1) * invS[x + k - 1] * inv64[k - 1];
            Ctab[k * NX + x] = c;
        }
    } else if (tid >= 128 && tid < 128 + NC * NC) {
        int id = tid - 128;
        int k = id / NC, i = id % NC;
        float acc = 0.0f;
#pragma unroll
        for (int j = 0; j < NC; j++)
            acc = __fmaf_rn(MC[j][k], cosM[j * NC + i], acc);
        Amat[k * NC + i] = acc;
    }
    __syncthreads();

    // ---- Stage 3: node values via Horner over C-table (180 threads) ----
    if (tid < NC * NX) {
        int i = tid / NX, x = tid % NX;
        float tn = cosf(PI * ((float)i + 0.5f) / (float)NC);
        float z  = ZC + ZH * tn;
        float acc = Ctab[(KSER - 1) * NX + x];
#pragma unroll
        for (int k = KSER - 2; k >= 0; k--)
            acc = __fmaf_rn(acc, z, Ctab[k * NX + x]);
        fnode[i * NX + x] = __logf(acc);
    }
    __syncthreads();

    // ---- Stage 4: sP = A * fnode (+ gsh folded into k=0) ----
    if (tid < NC * NX) {
        int k = tid / NX, x = tid % NX;
        float acc = (k == 0) ? gsh[x] : 0.0f;
#pragma unroll
        for (int i = 0; i < NC; i++)
            acc = __fmaf_rn(Amat[k * NC + i], fnode[i * NX + x], acc);
        sP[k * NX + x] = acc;
    }
    __syncthreads();

    // ---- Streaming main loop (software-pipelined, 4-elem groups) ----
    for (int cur = g; cur < ngroups; cur += stride) {
        int nxt = cur + stride;
        int4 xa2; float4 ta2, Ta2;
        if (nxt < ngroups) {                 // prefetch next group (3 LDG.128)
            xa2 = xin[nxt];
            ta2 = txin[nxt];
            Ta2 = Tin[nxt];
        }
        float4 o;
        o.x = eval_elem(xa.x, ta.x, Ta.x, r, alpha, r_la, c0, sP);
        o.y = eval_elem(xa.y, ta.y, Ta.y, r, alpha, r_la, c0, sP);
        o.z = eval_elem(xa.z, ta.z, Ta.z, r, alpha, r_la, c0, sP);
        o.w = eval_elem(xa.w, ta.w, Ta.w, r, alpha, r_la, c0, sP);
        out[cur] = o;
        xa = xa2; ta = ta2; Ta = Ta2;
    }

    // Tail (n % 4), handled by global thread 0.
    if (g == 0) {
        const int*   xsc = (const int*)xin;
        const float* tsc = (const float*)txin;
        const float* Tsc = (const float*)Tin;
        float*       osc = (float*)out;
        for (int e = ngroups << 2; e < n; e++)
            osc[e] = eval_elem(xsc[e], tsc[e], Tsc[e], r, alpha, r_la, c0, sP);
    }
}

extern "C" void kernel_launch(void* const* d_in, const int* in_sizes, int n_in,
                              void* d_out, int out_size) {
    const int*   x   = (const int*)d_in[0];
    const float* t_x = (const float*)d_in[1];
    const float* T   = (const float*)d_in[2];
    const float* lr  = (const float*)d_in[3];
    const float* lal = (const float*)d_in[4];
    const float* la  = (const float*)d_in[5];
    const float* lb  = (const float*)d_in[6];
    float* out = (float*)d_out;
    int n = in_sizes[0];

    int ngroups = n >> 2;
    int blocks = NBLOCKS;
    int needed = (ngroups + THREADS - 1) / THREADS;
    if (needed < blocks) blocks = needed;      // small-n safety
    if (blocks < 1) blocks = 1;
    bgnbd_kernel<<<blocks, THREADS>>>((const int4*)x, (const float4*)t_x,
                                      (const float4*)T, (float4*)out,
                                      lr, lal, la, lb, n);
}

// round 14
// speedup vs baseline: 1.3263x; 1.3263x over previous
#include <cuda_runtime.h>

#define NX     20      // x in [0, 20)
#define KSER   40      // fp32 series terms (setup); z<=0.75 tail ~1e-5
#define DEG    8       // polynomial degree of log(2F1) fit
#define NC     9       // DEG+1 coefficients / Chebyshev nodes
#define NINVS  59      // distinct 1/(a+b+j), j = x+k-1 in [0, 57]
// fit interval z in [0, 0.75]:  t = z*8/3 - 1
#define ZC     0.375f
#define ZH     0.375f
#define TSCALE 2.6666667f

#define THREADS 512
#define NBLOCKS 444    // 3 CTAs/SM x 148 SMs; single wave on 148- and 152-SM parts

// Chebyshev -> monomial conversion matrix, MC[j][k] = coeff of t^k in T_j (exact).
__constant__ float MC[NC][NC] = {
    { 1,  0,   0,    0,   0,    0,    0,    0,   0},
    { 0,  1,   0,    0,   0,    0,    0,    0,   0},
    {-1,  0,   2,    0,   0,    0,    0,    0,   0},
    { 0, -3,   0,    4,   0,    0,    0,    0,   0},
    { 1,  0,  -8,    0,   8,    0,    0,    0,   0},
    { 0,  5,   0,  -20,   0,   16,    0,    0,   0},
    {-1,  0,  18,    0, -48,    0,   32,    0,   0},
    { 0, -7,   0,   56,   0, -112,    0,   64,   0},
    { 1,  0, -32,    0, 160,    0, -256,    0, 128},
};

__device__ __forceinline__ float eval_elem(int x, float t_x, float T,
                                           float r, float alpha,
                                           float r_la, float c0,
                                           const float* sP) {
    float aT = T + alpha;
    float lT = __logf(aT);
    float dt = T - t_x;
    float z  = dt * __frcp_rn(aT);
    float lz = __logf(z);
    float t  = __fmaf_rn(z, TSCALE, -1.0f);
    const float* col = sP + x;                // x < NX guaranteed; stride NX over k
    float sacc = col[DEG * NX];
#pragma unroll
    for (int k = DEG - 1; k >= 0; k--)
        sacc = __fmaf_rn(sacc, t, col[k * NX]);
    float common = __fmaf_rn(-r, lT, r_la);
    float ll1 = __fmaf_rn(__int2float_rn(x), lz, common + sacc);
    float ll0 = common + c0;
    return (x == 0) ? ll0 : ll1;
}

__global__ __launch_bounds__(THREADS, 3) void bgnbd_kernel(
    const int4*   __restrict__ xin,
    const float4* __restrict__ txin,
    const float4* __restrict__ Tin,
    float4*       __restrict__ out,
    const float*  __restrict__ lr,
    const float*  __restrict__ lal,
    const float*  __restrict__ la,
    const float*  __restrict__ lb,
    int n)
{
    __shared__ float invS[NINVS];       // 1/(a+b+j)
    __shared__ float inv64[KSER];       // 1/(k+1)
    __shared__ float cosM[NC * NC];     // w_j * cos(pi j (i+0.5)/NC), [j][i]
    __shared__ float Amat[NC * NC];     // A[k][i] = sum_j MC[j][k] * cosM[j][i]
    __shared__ float Ctab[KSER * NX];   // series coeffs C_k(x), [k][x]
    __shared__ float fnode[NC * NX];    // log 2F1 at node i for x, [i][x]
    __shared__ float gsh[NX];           // lgamma combo per x
    __shared__ float sP[NC * NX];       // monomial coeffs (+gsh in k=0), [k][x]

    const float PI = 3.14159265358979323846f;
    int tid = threadIdx.x;

    int stride  = gridDim.x * blockDim.x;
    int ngroups = n >> 2;
    int g = blockIdx.x * blockDim.x + tid;

    // ---- Early prefetch of first group (3 LDG.128), overlaps setup ----
    int4 xa; float4 ta, Ta;
    if (g < ngroups) {
        xa = xin[g];
        ta = txin[g];
        Ta = Tin[g];
    }

    // Scalars (broadcast loads)
    float log_alpha = lal[0];
    float r     = __expf(lr[0]);
    float a     = __expf(la[0]);
    float b     = __expf(lb[0]);
    float alpha = __expf(log_alpha);
    float ab    = a + b;
    float r_la  = r * log_alpha;
    float c0    = logf(b) - logf(ab);

    // ---- Stage 1 (disjoint thread ranges, fully parallel) ----
    if (tid < NINVS) {
        invS[tid] = __frcp_rn(ab + (float)tid);
    } else if (tid >= 64 && tid < 64 + KSER) {
        int k = tid - 64;
        inv64[k] = __frcp_rn((float)(k + 1));
    } else if (tid >= 128 && tid < 128 + NC * NC) {
        int id = tid - 128;
        int j = id / NC, i = id % NC;
        float w = (j == 0) ? (1.0f / NC) : (2.0f / NC);
        cosM[id] = w * cosf(PI * (float)j * ((float)i + 0.5f) / (float)NC);
    } else if (tid >= 256 && tid < 256 + NX) {
        int x = tid - 256;
        float xf = (float)x;
        gsh[x] = lgammaf(r + xf) - lgammaf(r) - lgammaf(xf + 1.0f)
               + logf(a) + lgammaf(ab) - lgammaf(a)
               - lgammaf(ab + xf) + lgammaf(a + xf);
    }
    __syncthreads();

    // ---- Stage 2: serial C-table (threads 0-19)  ||  A = MC^T * cosM (threads 128+) ----
    if (tid < NX) {
        int x = tid;
        float xf = (float)x;
        float p = r + xf, q = a;
        float c = 1.0f;
        Ctab[0 * NX + x] = 1.0f;
        for (int k = 1; k < KSER; k++) {
            float km1 = (float)(k - 1);
            c *= (p + km1) * (q + km1) * invS[x + k - 1] * inv64[k - 1];
            Ctab[k * NX + x] = c;
        }
    } else if (tid >= 128 && tid < 128 + NC * NC) {
        int id = tid - 128;
        int k = id / NC, i = id % NC;
        float acc = 0.0f;
#pragma unroll
        for (int j = 0; j < NC; j++)
            acc = __fmaf_rn(MC[j][k], cosM[j * NC + i], acc);
        Amat[k * NC + i] = acc;
    }
    __syncthreads();

    // ---- Stage 3: node values via Horner over C-table (180 threads) ----
    if (tid < NC * NX) {
        int i = tid / NX, x = tid % NX;
        float tn = cosf(PI * ((float)i + 0.5f) / (float)NC);
        float z  = ZC + ZH * tn;
        float acc = Ctab[(KSER - 1) * NX + x];
#pragma unroll
        for (int k = KSER - 2; k >= 0; k--)
            acc = __fmaf_rn(acc, z, Ctab[k * NX + x]);
        fnode[i * NX + x] = __logf(acc);
    }
    __syncthreads();

    // ---- Stage 4: sP = A * fnode (+ gsh folded into k=0) ----
    if (tid < NC * NX) {
        int k = tid / NX, x = tid % NX;
        float acc = (k == 0) ? gsh[x] : 0.0f;
#pragma unroll
        for (int i = 0; i < NC; i++)
            acc = __fmaf_rn(Amat[k * NC + i], fnode[i * NX + x], acc);
        sP[k * NX + x] = acc;
    }
    __syncthreads();

    // ---- Streaming main loop (software-pipelined, 4-elem groups) ----
    for (int cur = g; cur < ngroups; cur += stride) {
        int nxt = cur + stride;
        int4 xa2; float4 ta2, Ta2;
        if (nxt < ngroups) {                 // prefetch next group (3 LDG.128)
            xa2 = xin[nxt];
            ta2 = txin[nxt];
            Ta2 = Tin[nxt];
        }
        float4 o;
        o.x = eval_elem(xa.x, ta.x, Ta.x, r, alpha, r_la, c0, sP);
        o.y = eval_elem(xa.y, ta.y, Ta.y, r, alpha, r_la, c0, sP);
        o.z = eval_elem(xa.z, ta.z, Ta.z, r, alpha, r_la, c0, sP);
        o.w = eval_elem(xa.w, ta.w, Ta.w, r, alpha, r_la, c0, sP);
        out[cur] = o;
        xa = xa2; ta = ta2; Ta = Ta2;
    }

    // Tail (n % 4), handled by global thread 0.
    if (g == 0) {
        const int*   xsc = (const int*)xin;
        const float* tsc = (const float*)txin;
        const float* Tsc = (const float*)Tin;
        float*       osc = (float*)out;
        for (int e = ngroups << 2; e < n; e++)
            osc[e] = eval_elem(xsc[e], tsc[e], Tsc[e], r, alpha, r_la, c0, sP);
    }
}

extern "C" void kernel_launch(void* const* d_in, const int* in_sizes, int n_in,
                              void* d_out, int out_size) {
    const int*   x   = (const int*)d_in[0];
    const float* t_x = (const float*)d_in[1];
    const float* T   = (const float*)d_in[2];
    const float* lr  = (const float*)d_in[3];
    const float* lal = (const float*)d_in[4];
    const float* la  = (const float*)d_in[5];
    const float* lb  = (const float*)d_in[6];
    float* out = (float*)d_out;
    int n = in_sizes[0];

    int ngroups = n >> 2;
    int blocks = NBLOCKS;
    int needed = (ngroups + THREADS - 1) / THREADS;
    if (needed < blocks) blocks = needed;      // small-n safety
    if (blocks < 1) blocks = 1;
    bgnbd_kernel<<<blocks, THREADS>>>((const int4*)x, (const float4*)t_x,
                                      (const float4*)T, (float4*)out,
                                      lr, lal, la, lb, n);
}

// round 15
// speedup vs baseline: 1.4061x; 1.0602x over previous
#include <cuda_runtime.h>

#define NX     20      // x in [0, 20)
#define KSER   40      // fp32 series terms (setup); z<=0.75 tail ~1e-5
#define DEG    8       // polynomial degree of log(2F1) fit
#define NC     9       // DEG+1 coefficients / Chebyshev nodes
#define NINVS  59      // distinct 1/(a+b+j), j = x+k-1 in [0, 57]
// fit interval z in [0, 0.75]:  t = z*8/3 - 1
#define ZC     0.375f
#define ZH     0.375f
#define TSCALE 2.6666667f

#define THREADS 512
#define NBLOCKS 444    // 3 CTAs/SM x 148 SMs; single wave on 148- and 152-SM parts

// Chebyshev -> monomial conversion matrix, MC[j][k] = coeff of t^k in T_j (exact).
__constant__ float MC[NC][NC] = {
    { 1,  0,   0,    0,   0,    0,    0,    0,   0},
    { 0,  1,   0,    0,   0,    0,    0,    0,   0},
    {-1,  0,   2,    0,   0,    0,    0,    0,   0},
    { 0, -3,   0,    4,   0,    0,    0,    0,   0},
    { 1,  0,  -8,    0,   8,    0,    0,    0,   0},
    { 0,  5,   0,  -20,   0,   16,    0,    0,   0},
    {-1,  0,  18,    0, -48,    0,   32,    0,   0},
    { 0, -7,   0,   56,   0, -112,    0,   64,   0},
    { 1,  0, -32,    0, 160,    0, -256,    0, 128},
};

__device__ __forceinline__ float eval_elem(int x, float t_x, float T,
                                           float r, float alpha,
                                           float r_la, float c0,
                                           const float* sP) {
    float aT = T + alpha;
    float lT = __logf(aT);
    float dt = T - t_x;
    float z  = __fdividef(dt, aT);            // MUFU.RCP + FMUL (fast path)
    float lz = __logf(z);
    float t  = __fmaf_rn(z, TSCALE, -1.0f);
    const float* col = sP + x;                // x < NX guaranteed; stride NX over k
    float sacc = col[DEG * NX];
#pragma unroll
    for (int k = DEG - 1; k >= 0; k--)
        sacc = __fmaf_rn(sacc, t, col[k * NX]);
    float common = __fmaf_rn(-r, lT, r_la);
    float ll1 = __fmaf_rn(__int2float_rn(x), lz, common + sacc);
    float ll0 = common + c0;
    return (x == 0) ? ll0 : ll1;
}

__global__ __launch_bounds__(THREADS, 3) void bgnbd_kernel(
    const int4*   __restrict__ xin,
    const float4* __restrict__ txin,
    const float4* __restrict__ Tin,
    float4*       __restrict__ out,
    const float*  __restrict__ lr,
    const float*  __restrict__ lal,
    const float*  __restrict__ la,
    const float*  __restrict__ lb,
    int n)
{
    __shared__ float invS[NINVS];       // 1/(a+b+j)
    __shared__ float inv64[KSER];       // 1/(k+1)
    __shared__ float cosM[NC * NC];     // w_j * cos(pi j (i+0.5)/NC), [j][i]
    __shared__ float Amat[NC * NC];     // A[k][i] = sum_j MC[j][k] * cosM[j][i]
    __shared__ float Ctab[KSER * NX];   // series coeffs C_k(x), [k][x]
    __shared__ float fnode[NC * NX];    // log 2F1 at node i for x, [i][x]
    __shared__ float gsh[NX];           // lgamma combo per x
    __shared__ float sP[NC * NX];       // monomial coeffs (+gsh in k=0), [k][x]

    const float PI = 3.14159265358979323846f;
    int tid = threadIdx.x;

    int stride  = gridDim.x * blockDim.x;
    int ngroups = n >> 2;
    int g = blockIdx.x * blockDim.x + tid;

    // ---- Early prefetch of first group (3 LDG.128, evict-first), overlaps setup ----
    int4 xa; float4 ta, Ta;
    if (g < ngroups) {
        xa = __ldcs(&xin[g]);
        ta = __ldcs(&txin[g]);
        Ta = __ldcs(&Tin[g]);
    }

    // Scalars (broadcast loads)
    float log_alpha = lal[0];
    float r     = __expf(lr[0]);
    float a     = __expf(la[0]);
    float b     = __expf(lb[0]);
    float alpha = __expf(log_alpha);
    float ab    = a + b;
    float r_la  = r * log_alpha;
    float c0    = logf(b) - logf(ab);

    // ---- Stage 1 (disjoint thread ranges, fully parallel) ----
    if (tid < NINVS) {
        invS[tid] = __frcp_rn(ab + (float)tid);
    } else if (tid >= 64 && tid < 64 + KSER) {
        int k = tid - 64;
        inv64[k] = __frcp_rn((float)(k + 1));
    } else if (tid >= 128 && tid < 128 + NC * NC) {
        int id = tid - 128;
        int j = id / NC, i = id % NC;
        float w = (j == 0) ? (1.0f / NC) : (2.0f / NC);
        cosM[id] = w * cosf(PI * (float)j * ((float)i + 0.5f) / (float)NC);
    } else if (tid >= 256 && tid < 256 + NX) {
        int x = tid - 256;
        float xf = (float)x;
        gsh[x] = lgammaf(r + xf) - lgammaf(r) - lgammaf(xf + 1.0f)
               + logf(a) + lgammaf(ab) - lgammaf(a)
               - lgammaf(ab + xf) + lgammaf(a + xf);
    }
    __syncthreads();

    // ---- Stage 2: serial C-table (threads 0-19)  ||  A = MC^T * cosM (threads 128+) ----
    if (tid < NX) {
        int x = tid;
        float xf = (float)x;
        float p = r + xf, q = a;
        float c = 1.0f;
        Ctab[0 * NX + x] = 1.0f;
        for (int k = 1; k < KSER; k++) {
            float km1 = (float)(k - 1);
            c *= (p + km1) * (q + km1) * invS[x + k - 1] * inv64[k - 1];
            Ctab[k * NX + x] = c;
        }
    } else if (tid >= 128 && tid < 128 + NC * NC) {
        int id = tid - 128;
        int k = id / NC, i = id % NC;
        float acc = 0.0f;
#pragma unroll
        for (int j = 0; j < NC; j++)
            acc = __fmaf_rn(MC[j][k], cosM[j * NC + i], acc);
        Amat[k * NC + i] = acc;
    }
    __syncthreads();

    // ---- Stage 3: node values via Horner over C-table (180 threads) ----
    if (tid < NC * NX) {
        int i = tid / NX, x = tid % NX;
        float tn = cosf(PI * ((float)i + 0.5f) / (float)NC);
        float z  = ZC + ZH * tn;
        float acc = Ctab[(KSER - 1) * NX + x];
#pragma unroll
        for (int k = KSER - 2; k >= 0; k--)
            acc = __fmaf_rn(acc, z, Ctab[k * NX + x]);
        fnode[i * NX + x] = __logf(acc);
    }
    __syncthreads();

    // ---- Stage 4: sP = A * fnode (+ gsh folded into k=0) ----
    if (tid < NC * NX) {
        int k = tid / NX, x = tid % NX;
        float acc = (k == 0) ? gsh[x] : 0.0f;
#pragma unroll
        for (int i = 0; i < NC; i++)
            acc = __fmaf_rn(Amat[k * NC + i], fnode[i * NX + x], acc);
        sP[k * NX + x] = acc;
    }
    __syncthreads();

    // ---- Streaming main loop (software-pipelined, 4-elem groups) ----
    for (int cur = g; cur < ngroups; cur += stride) {
        int nxt = cur + stride;
        int4 xa2; float4 ta2, Ta2;
        if (nxt < ngroups) {                 // prefetch next group (3 LDG.128)
            xa2 = __ldcs(&xin[nxt]);
            ta2 = __ldcs(&txin[nxt]);
            Ta2 = __ldcs(&Tin[nxt]);
        }
        float4 o;
        o.x = eval_elem(xa.x, ta.x, Ta.x, r, alpha, r_la, c0, sP);
        o.y = eval_elem(xa.y, ta.y, Ta.y, r, alpha, r_la, c0, sP);
        o.z = eval_elem(xa.z, ta.z, Ta.z, r, alpha, r_la, c0, sP);
        o.w = eval_elem(xa.w, ta.w, Ta.w, r, alpha, r_la, c0, sP);
        __stcs(&out[cur], o);
        xa = xa2; ta = ta2; Ta = Ta2;
    }

    // Tail (n % 4), handled by global thread 0.
    if (g == 0) {
        const int*   xsc = (const int*)xin;
        const float* tsc = (const float*)txin;
        const float* Tsc = (const float*)Tin;
        float*       osc = (float*)out;
        for (int e = ngroups << 2; e < n; e++)
            osc[e] = eval_elem(xsc[e], tsc[e], Tsc[e], r, alpha, r_la, c0, sP);
    }
}

extern "C" void kernel_launch(void* const* d_in, const int* in_sizes, int n_in,
                              void* d_out, int out_size) {
    const int*   x   = (const int*)d_in[0];
    const float* t_x = (const float*)d_in[1];
    const float* T   = (const float*)d_in[2];
    const float* lr  = (const float*)d_in[3];
    const float* lal = (const float*)d_in[4];
    const float* la  = (const float*)d_in[5];
    const float* lb  = (const float*)d_in[6];
    float* out = (float*)d_out;
    int n = in_sizes[0];

    int ngroups = n >> 2;
    int blocks = NBLOCKS;
    int needed = (ngroups + THREADS - 1) / THREADS;
    if (needed < blocks) blocks = needed;      // small-n safety
    if (blocks < 1) blocks = 1;
    bgnbd_kernel<<<blocks, THREADS>>>((const int4*)x, (const float4*)t_x,
                                      (const float4*)T, (float4*)out,
                                      lr, lal, la, lb, n);
}